// round 12
// baseline (speedup 1.0000x reference)
#include <cuda_runtime.h>

// FINAL (converged): Bilinear 2x upsample, NHWC f32, 2x2-output-per-thread.
// in : (8, 256, 256, 64), out: (8, 512, 512, 64)
//
// At the measured hardware ceiling: 611 MB/replay compulsory traffic
// (537 MB writes + ~74 MB cross-replay residual reads) at ~6.35 TB/s
// sustained mixed-stream bandwidth -> 96.2 us floor == measured ncu time.
// Eleven variants (wavefront reduction, 256-bit LDG/STG, L2 evict policies,
// persistent launch, occupancy 33-81%, store hints) all confirmed this wall.

static constexpr int IN_H  = 256;
static constexpr int IN_W  = 256;
static constexpr int OUT_H = 512;
static constexpr int OUT_W = 512;
static constexpr int CV    = 16;   // float4 vectors per pixel (C=64)

__device__ __forceinline__ float4 lerp4(float4 a, float4 b, float wb) {
    float wa = 1.0f - wb;
    float4 r;
    r.x = a.x * wa + b.x * wb;
    r.y = a.y * wa + b.y * wb;
    r.z = a.z * wa + b.z * wb;
    r.w = a.w * wa + b.w * wb;
    return r;
}

__global__ __launch_bounds__(256)
void bilerp2x_final_kernel(const float4* __restrict__ in, float4* __restrict__ out) {
    int cvec = threadIdx.x;                      // 0..15 : channel chunk
    int i    = blockIdx.x * 16 + threadIdx.y;    // column group, 0..256
    int j    = blockIdx.y;                       // row group, 0..256
    int b    = blockIdx.z;
    if (i > 256) return;

    int ii = i - 1;                              // input col pair base
    int jj = j - 1;                              // input row pair base
    int x_lo = max(ii, 0);
    int x_hi = min(ii + 1, IN_W - 1);
    int y_lo = max(jj, 0);
    int y_hi = min(jj + 1, IN_H - 1);

    long in_b = (long)b * IN_H * IN_W * CV;
    const float4* r0 = in + in_b + (long)(y_lo * IN_W) * CV + cvec;
    const float4* r1 = in + in_b + (long)(y_hi * IN_W) * CV + cvec;

    float4 p00 = __ldg(r0 + (long)x_lo * CV);
    float4 p01 = __ldg(r0 + (long)x_hi * CV);
    float4 p10 = __ldg(r1 + (long)x_lo * CV);
    float4 p11 = __ldg(r1 + (long)x_hi * CV);

    // horizontal lerps: ox_a = 2i-1 -> dx=0.25 ; ox_b = 2i -> dx=0.75
    float4 ta = lerp4(p00, p01, 0.25f);
    float4 tb = lerp4(p00, p01, 0.75f);
    float4 ba = lerp4(p10, p11, 0.25f);
    float4 bb = lerp4(p10, p11, 0.75f);

    int ox_a = 2 * i - 1;
    int ox_b = 2 * i;
    int oy_a = 2 * j - 1;
    int oy_b = 2 * j;

    bool wxa = (i >= 1);
    bool wxb = (i <= 255);
    bool wya = (j >= 1);
    bool wyb = (j <= 255);

    long out_b = (long)b * OUT_H * OUT_W * CV + cvec;

    if (wya) {  // output row oy_a, dy = 0.25
        long row = out_b + (long)(oy_a * OUT_W) * CV;
        if (wxa) out[row + (long)ox_a * CV] = lerp4(ta, ba, 0.25f);
        if (wxb) out[row + (long)ox_b * CV] = lerp4(tb, bb, 0.25f);
    }
    if (wyb) {  // output row oy_b, dy = 0.75
        long row = out_b + (long)(oy_b * OUT_W) * CV;
        if (wxa) out[row + (long)ox_a * CV] = lerp4(ta, ba, 0.75f);
        if (wxb) out[row + (long)ox_b * CV] = lerp4(tb, bb, 0.75f);
    }
}

extern "C" void kernel_launch(void* const* d_in, const int* in_sizes, int n_in,
                              void* d_out, int out_size) {
    const float4* in  = (const float4*)d_in[0];
    float4*       out = (float4*)d_out;

    dim3 block(16, 16);                 // tx = channel chunk, ty = column group
    dim3 grid(17, 257, 8);              // 257 column groups, 257 row groups, 8 batches
    bilerp2x_final_kernel<<<grid, block>>>(in, out);
}

// round 13
// speedup vs baseline: 1.0096x; 1.0096x over previous
#include <cuda_runtime.h>

// Bilinear 2x upsample, NHWC f32, 2x2-output-per-thread (converged R2/R6 body).
// Final launch-shape A/B: 512-thread CTAs (32 column groups x 16 channel
// chunks) — halves CTA count, widens per-CTA contiguous footprint to 8 KB
// per row for better L2/DRAM page locality. Same per-thread instruction
// stream, same compulsory traffic (611 MB/replay at the ~6.35 TB/s wall).
// in : (8, 256, 256, 64), out: (8, 512, 512, 64)

static constexpr int IN_H  = 256;
static constexpr int IN_W  = 256;
static constexpr int OUT_H = 512;
static constexpr int OUT_W = 512;
static constexpr int CV    = 16;   // float4 vectors per pixel (C=64)

__device__ __forceinline__ float4 lerp4(float4 a, float4 b, float wb) {
    float wa = 1.0f - wb;
    float4 r;
    r.x = a.x * wa + b.x * wb;
    r.y = a.y * wa + b.y * wb;
    r.z = a.z * wa + b.z * wb;
    r.w = a.w * wa + b.w * wb;
    return r;
}

__global__ __launch_bounds__(512)
void bilerp2x_b512_kernel(const float4* __restrict__ in, float4* __restrict__ out) {
    int cvec = threadIdx.x;                      // 0..15 : channel chunk
    int i    = blockIdx.x * 32 + threadIdx.y;    // column group, 0..256 (ty 0..31)
    int j    = blockIdx.y;                       // row group, 0..256
    int b    = blockIdx.z;
    if (i > 256) return;

    int ii = i - 1;                              // input col pair base
    int jj = j - 1;                              // input row pair base
    int x_lo = max(ii, 0);
    int x_hi = min(ii + 1, IN_W - 1);
    int y_lo = max(jj, 0);
    int y_hi = min(jj + 1, IN_H - 1);

    long in_b = (long)b * IN_H * IN_W * CV;
    const float4* r0 = in + in_b + (long)(y_lo * IN_W) * CV + cvec;
    const float4* r1 = in + in_b + (long)(y_hi * IN_W) * CV + cvec;

    float4 p00 = __ldg(r0 + (long)x_lo * CV);
    float4 p01 = __ldg(r0 + (long)x_hi * CV);
    float4 p10 = __ldg(r1 + (long)x_lo * CV);
    float4 p11 = __ldg(r1 + (long)x_hi * CV);

    // horizontal lerps: ox_a = 2i-1 -> dx=0.25 ; ox_b = 2i -> dx=0.75
    float4 ta = lerp4(p00, p01, 0.25f);
    float4 tb = lerp4(p00, p01, 0.75f);
    float4 ba = lerp4(p10, p11, 0.25f);
    float4 bb = lerp4(p10, p11, 0.75f);

    int ox_a = 2 * i - 1;
    int ox_b = 2 * i;
    int oy_a = 2 * j - 1;
    int oy_b = 2 * j;

    bool wxa = (i >= 1);
    bool wxb = (i <= 255);
    bool wya = (j >= 1);
    bool wyb = (j <= 255);

    long out_b = (long)b * OUT_H * OUT_W * CV + cvec;

    if (wya) {  // output row oy_a, dy = 0.25
        long row = out_b + (long)(oy_a * OUT_W) * CV;
        if (wxa) out[row + (long)ox_a * CV] = lerp4(ta, ba, 0.25f);
        if (wxb) out[row + (long)ox_b * CV] = lerp4(tb, bb, 0.25f);
    }
    if (wyb) {  // output row oy_b, dy = 0.75
        long row = out_b + (long)(oy_b * OUT_W) * CV;
        if (wxa) out[row + (long)ox_a * CV] = lerp4(ta, ba, 0.75f);
        if (wxb) out[row + (long)ox_b * CV] = lerp4(tb, bb, 0.75f);
    }
}

extern "C" void kernel_launch(void* const* d_in, const int* in_sizes, int n_in,
                              void* d_out, int out_size) {
    const float4* in  = (const float4*)d_in[0];
    float4*       out = (float4*)d_out;

    dim3 block(16, 32);                 // 512 threads: tx = channel chunk, ty = column group
    dim3 grid(9, 257, 8);               // 9*32 = 288 >= 257 column groups
    bilerp2x_b512_kernel<<<grid, block>>>(in, out);
}

// round 14
// speedup vs baseline: 1.0099x; 1.0003x over previous
#include <cuda_runtime.h>

// Bilinear 2x upsample, NHWC f32, 2x2-output-per-thread, 512-thread CTAs,
// FLATTENED exact-cover launch: tile space (b,j,i) = 8 x 257 x 257 units is
// linearized; each block covers 32 consecutive units (16 threads each), so
// idle thread slots drop from 10.8% (ragged 9x32 grid) to 0.005%.
// in : (8, 256, 256, 64), out: (8, 512, 512, 64)

static constexpr int IN_H  = 256;
static constexpr int IN_W  = 256;
static constexpr int OUT_H = 512;
static constexpr int OUT_W = 512;
static constexpr int CV    = 16;            // float4 vectors per pixel (C=64)
static constexpr int NI    = 257;           // column groups
static constexpr int NJ    = 257;           // row groups
static constexpr int NB    = 8;             // batches
static constexpr int NUNIT = NI * NJ * NB;  // 528392 tile units
static constexpr int UPB   = 32;            // units per block (512 threads / 16)

__device__ __forceinline__ float4 lerp4(float4 a, float4 b, float wb) {
    float wa = 1.0f - wb;
    float4 r;
    r.x = a.x * wa + b.x * wb;
    r.y = a.y * wa + b.y * wb;
    r.z = a.z * wa + b.z * wb;
    r.w = a.w * wa + b.w * wb;
    return r;
}

__global__ __launch_bounds__(512)
void bilerp2x_flat_kernel(const float4* __restrict__ in, float4* __restrict__ out) {
    int cvec = threadIdx.x;                         // 0..15 : channel chunk
    int unit = blockIdx.x * UPB + threadIdx.y;      // tile unit id
    if (unit >= NUNIT) return;

    // decompose unit -> (b, j, i), i fastest (row-major store locality)
    int b   = unit / (NI * NJ);
    int rem = unit - b * (NI * NJ);
    int j   = rem / NI;
    int i   = rem - j * NI;                         // 0..256

    int ii = i - 1;
    int jj = j - 1;
    int x_lo = max(ii, 0);
    int x_hi = min(ii + 1, IN_W - 1);
    int y_lo = max(jj, 0);
    int y_hi = min(jj + 1, IN_H - 1);

    long in_b = (long)b * IN_H * IN_W * CV;
    const float4* r0 = in + in_b + (long)(y_lo * IN_W) * CV + cvec;
    const float4* r1 = in + in_b + (long)(y_hi * IN_W) * CV + cvec;

    float4 p00 = __ldg(r0 + (long)x_lo * CV);
    float4 p01 = __ldg(r0 + (long)x_hi * CV);
    float4 p10 = __ldg(r1 + (long)x_lo * CV);
    float4 p11 = __ldg(r1 + (long)x_hi * CV);

    // horizontal lerps: ox_a = 2i-1 -> dx=0.25 ; ox_b = 2i -> dx=0.75
    float4 ta = lerp4(p00, p01, 0.25f);
    float4 tb = lerp4(p00, p01, 0.75f);
    float4 ba = lerp4(p10, p11, 0.25f);
    float4 bb = lerp4(p10, p11, 0.75f);

    int ox_a = 2 * i - 1;
    int ox_b = 2 * i;
    int oy_a = 2 * j - 1;
    int oy_b = 2 * j;

    bool wxa = (i >= 1);
    bool wxb = (i <= 255);
    bool wya = (j >= 1);
    bool wyb = (j <= 255);

    long out_b = (long)b * OUT_H * OUT_W * CV + cvec;

    if (wya) {  // output row oy_a, dy = 0.25
        long row = out_b + (long)(oy_a * OUT_W) * CV;
        if (wxa) out[row + (long)ox_a * CV] = lerp4(ta, ba, 0.25f);
        if (wxb) out[row + (long)ox_b * CV] = lerp4(tb, bb, 0.25f);
    }
    if (wyb) {  // output row oy_b, dy = 0.75
        long row = out_b + (long)(oy_b * OUT_W) * CV;
        if (wxa) out[row + (long)ox_a * CV] = lerp4(ta, ba, 0.75f);
        if (wxb) out[row + (long)ox_b * CV] = lerp4(tb, bb, 0.75f);
    }
}

extern "C" void kernel_launch(void* const* d_in, const int* in_sizes, int n_in,
                              void* d_out, int out_size) {
    const float4* in  = (const float4*)d_in[0];
    float4*       out = (float4*)d_out;

    dim3 block(16, 32);                              // 512 threads
    dim3 grid((NUNIT + UPB - 1) / UPB);              // 16513 blocks, exact cover
    bilerp2x_flat_kernel<<<grid, block>>>(in, out);
}